// round 15
// baseline (speedup 1.0000x reference)
#include <cuda_runtime.h>
#include <cstdint>

// ---------------------------------------------------------------------------
// PConvLinear, both stages on fp16 mma.sync (m16n8k16), fp32 accumulate.
//   out[p,o] = bias[o] + sum_f P[p,f] * W[o,f],  f = c*16 + m
//   P[p, c*16+m] = sum_{k<16} feat[p,k,c] * wn[p,k,m]
// R15: pconv phase folded into the main GEMM. P double-buffered; per group:
//   phase A (s=0..7): GEMM(g) + gather(g+1)        -> sync
//   phase B (s=8..15): GEMM(g) + pconv(g+1)->P[~]  -> sync
// A tiles 512B/pt chunk-swizzled (c' = c ^ (c>>3)): ldsm conflict-free.
// Wfrag prefetch distance 2 carried across groups; group 4 = 3 real s-steps.
// ---------------------------------------------------------------------------

#define NPTS 120000
#define NB   60000
#define TPB  64
#define THREADS 256
#define GRID (NPTS / TPB)      // 1875

#define PROWB 528
#define PBUFB (64 * PROWB)     // 33792
#define OFF_A    (2 * PBUFB)   // 67584  (A: 64 pts x 512B, chunk-swizzled)
#define OFF_IND  100352
#define OFF_BIAS 104448
#define SMEM_BYTES 104960      // <= 114688 -> 2 CTAs/SM

// W fragments: [fs 80][wn4 4][q*128 + l*4]
__device__ uint32_t Wfrag[80 * 1024];

__device__ __forceinline__ uint32_t smem_u32(const void* p) {
    uint32_t a;
    asm("{ .reg .u64 t; cvta.to.shared.u64 t, %1; cvt.u32.u64 %0, t; }"
        : "=r"(a) : "l"(p));
    return a;
}
__device__ __forceinline__ uint32_t pack_f16x2(float lo, float hi) {
    uint32_t r;
    asm("cvt.rn.f16x2.f32 %0, %1, %2;" : "=r"(r) : "f"(hi), "f"(lo));
    return r;
}
__device__ __forceinline__ void ldsm4(uint32_t r[4], uint32_t addr) {
    asm volatile("ldmatrix.sync.aligned.m8n8.x4.shared.b16 {%0,%1,%2,%3}, [%4];"
                 : "=r"(r[0]), "=r"(r[1]), "=r"(r[2]), "=r"(r[3]) : "r"(addr));
}
__device__ __forceinline__ void mma16(float c[4], const uint32_t a[4],
                                      uint32_t b0, uint32_t b1) {
    asm volatile(
        "mma.sync.aligned.m16n8k16.row.col.f32.f16.f16.f32 "
        "{%0,%1,%2,%3}, {%4,%5,%6,%7}, {%8,%9}, {%0,%1,%2,%3};"
        : "+f"(c[0]), "+f"(c[1]), "+f"(c[2]), "+f"(c[3])
        : "r"(a[0]), "r"(a[1]), "r"(a[2]), "r"(a[3]), "r"(b0), "r"(b1));
}

// ---- prep: analytic fp16 B fragments of W (proven) ----
extern "C" __global__ void __launch_bounds__(128, 1)
prep_kernel(const float* __restrict__ W) {
    const int bg = blockIdx.x;           // fs = g*16 + s
    const int t = threadIdx.x, l = t & 31, wn4 = t >> 5;
    const int f0 = (bg >> 4) * 256 + (bg & 15) * 16 + 2 * (l & 3);
    uint32_t r[8];
    #pragma unroll
    for (int nt = 0; nt < 4; ++nt) {
        int o = wn4 * 32 + nt * 8 + (l >> 2);
        const float* wr = W + (size_t)o * 1072;
        float v0 = (f0     < 1072) ? wr[f0]     : 0.f;
        float v1 = (f0 + 1 < 1072) ? wr[f0 + 1] : 0.f;
        float v2 = (f0 + 8 < 1072) ? wr[f0 + 8] : 0.f;
        float v3 = (f0 + 9 < 1072) ? wr[f0 + 9] : 0.f;
        r[nt * 2 + 0] = pack_f16x2(v0, v1);
        r[nt * 2 + 1] = pack_f16x2(v2, v3);
    }
    uint32_t* dst = Wfrag + (bg * 4 + wn4) * 256 + l * 4;
    *(uint4*)dst         = make_uint4(r[0], r[1], r[2], r[3]);
    *(uint4*)(dst + 128) = make_uint4(r[4], r[5], r[6], r[7]);
}

// ---- main ----
extern "C" __global__ void __launch_bounds__(THREADS, 2)
pcl_kernel(const float* __restrict__ xin,   // [2,60000,64]
           const int*   __restrict__ nbr,   // [2,60000,16]
           const float* __restrict__ wng,   // [2,60000,16,16]
           const float* __restrict__ addf,  // [2,60000,16,3]
           const float* __restrict__ bias,  // [128]
           float*       __restrict__ out)   // [2,60000,128]
{
    extern __shared__ __align__(16) char smc[];
    int*   inds = (int*)(smc + OFF_IND);
    float* bsm  = (float*)(smc + OFF_BIAS);

    const uint32_t smb = smem_u32(smc);
    const int t    = threadIdx.x;
    const int wid  = t >> 5;
    const int l    = t & 31;
    const int base = blockIdx.x * TPB;

    // main-GEMM roles
    const int wm  = wid & 1;
    const int wn4 = wid >> 1;

    if (t < 128) bsm[t] = bias[t];

    // ---- neighbor indices: 64 pts x 16 ----
    {
        int pt = base + (t >> 2);
        ((int4*)inds)[t] = *(const int4*)(nbr + (size_t)pt * 16 + (size_t)(t & 3) * 4);
    }

    // ---- pconv B fragments: warp's 8 points, per m-half, from wng ----
    uint32_t bw[8][2][2];
    {
        const int c2 = 2 * (l & 3);
        const int nl = l >> 2;
        #pragma unroll
        for (int j = 0; j < 8; ++j) {
            const float* wp = wng + (size_t)(base + wid * 8 + j) * 256;
            #pragma unroll
            for (int h = 0; h < 2; ++h) {
                int m = h * 8 + nl;
                bw[j][h][0] = pack_f16x2(wp[c2 * 16 + m],       wp[(c2 + 1) * 16 + m]);
                bw[j][h][1] = pack_f16x2(wp[(c2 + 8) * 16 + m], wp[(c2 + 9) * 16 + m]);
            }
        }
    }

    float acc[2][4][4];
    #pragma unroll
    for (int i = 0; i < 2; ++i)
        #pragma unroll
        for (int j = 0; j < 4; ++j)
            #pragma unroll
            for (int q = 0; q < 4; ++q) acc[i][j][q] = 0.f;

    // ---- gather roles (fixed); A chunk-swizzle offsets per thread ----
    const int gw  = t & 3;
    const int gkp = (t >> 2) & 7;
    const int gp8 = t >> 5;
    uint32_t gOff[4];
    #pragma unroll
    for (int cw = 0; cw < 4; ++cw) {
        int r = gw * 4 + cw;
        int c = 2 * r + (gkp >> 2);
        int cp = c ^ (c >> 3);
        gOff[cw] = (uint32_t)(cp * 16 + (gkp & 3) * 4);
    }

    auto gatherLDG = [&](int gg, int rep, float4& va, float4& vb) {
        int pp  = rep * 8 + gp8;
        int pid = base + pp;
        if (gg < 4) {
            int k0   = 2 * gkp;
            int nb0  = inds[pp * 16 + k0];
            int nb1  = inds[pp * 16 + k0 + 1];
            int brow = (pid >= NB) ? NB : 0;
            va = *(const float4*)(xin + (size_t)(brow + nb0) * 64 + gg * 16 + gw * 4);
            vb = *(const float4*)(xin + (size_t)(brow + nb1) * 64 + gg * 16 + gw * 4);
        } else {
            va = make_float4(0.f, 0.f, 0.f, 0.f);
            vb = make_float4(0.f, 0.f, 0.f, 0.f);
            if (gw == 0) {
                const float* a0 = addf + ((size_t)pid * 16 + 2 * gkp) * 3;
                va.x = a0[0]; va.y = a0[1]; va.z = a0[2];
                vb.x = a0[3]; vb.y = a0[4]; vb.z = a0[5];
            }
        }
    };
    auto gatherSTS = [&](int rep, const float4& va, const float4& vb) {
        char* ab = smc + OFF_A + (rep * 8 + gp8) * 512;
        *(uint32_t*)(ab + gOff[0]) = pack_f16x2(va.x, vb.x);
        *(uint32_t*)(ab + gOff[1]) = pack_f16x2(va.y, vb.y);
        *(uint32_t*)(ab + gOff[2]) = pack_f16x2(va.z, vb.z);
        *(uint32_t*)(ab + gOff[3]) = pack_f16x2(va.w, vb.w);
    };

    // pconv role constants (ldsm on swizzled A)
    uint32_t aoffA;
    {
        int c = 2 * (l & 15) + (l >> 4);
        aoffA = (uint32_t)((c ^ (c >> 3)) * 16);
    }
    const int rr = l >> 2;
    const int mc = 2 * (l & 3);

    auto pconvPt = [&](int j, char* pdst) {
        int ptl = wid * 8 + j;
        uint32_t a[4];
        ldsm4(a, smb + OFF_A + (uint32_t)(ptl * 512) + aoffA);
        char* prow = pdst + ptl * PROWB;
        #pragma unroll
        for (int h = 0; h < 2; ++h) {
            float c[4] = {0.f, 0.f, 0.f, 0.f};
            mma16(c, a, bw[j][h][0], bw[j][h][1]);
            int fl = rr * 16 + h * 8 + mc;
            *(uint32_t*)(prow + fl * 2)         = pack_f16x2(c[0], c[1]);
            *(uint32_t*)(prow + (fl + 128) * 2) = pack_f16x2(c[2], c[3]);
        }
    };

    // main-GEMM A address (row within P buffer)
    const uint32_t arow = smb + (uint32_t)((wm * 32 + (l & 15)) * PROWB
                                           + (l >> 4) * 16);

    auto mmaStep = [&](uint32_t pb, int s, const uint4& U0, const uint4& U1) {
        #pragma unroll
        for (int mt = 0; mt < 2; ++mt) {
            uint32_t a[4];
            ldsm4(a, arow + pb + (uint32_t)(mt * 16 * PROWB + s * 32));
            mma16(acc[mt][0], a, U0.x, U0.y);
            mma16(acc[mt][1], a, U0.z, U0.w);
            mma16(acc[mt][2], a, U1.x, U1.y);
            mma16(acc[mt][3], a, U1.z, U1.w);
        }
    };

    __syncthreads();   // inds visible

    // ---- prologue: gather(0) ----
    #pragma unroll
    for (int rep = 0; rep < 8; ++rep) {
        float4 va, vb;
        gatherLDG(0, rep, va, vb);
        gatherSTS(rep, va, vb);
    }

    // ---- Wfrag rolling prefetch slots: fs 0 and 1 ----
    const uint32_t* wfl = Wfrag + wn4 * 256 + l * 4;
    uint4 u[2][2];
    u[0][0] = *(const uint4*)wfl;
    u[0][1] = *(const uint4*)(wfl + 128);
    u[1][0] = *(const uint4*)(wfl + 1024);
    u[1][1] = *(const uint4*)(wfl + 1024 + 128);

    __syncthreads();   // A(0) ready

    // ---- prologue: pconv(0) -> P[0] ----
    #pragma unroll
    for (int j = 0; j < 8; ++j) pconvPt(j, smc);
    __syncthreads();   // P[0] ready

    for (int g = 0; g < 4; ++g) {
        const uint32_t pb = (uint32_t)((g & 1) * PBUFB);
        const uint32_t* wfg = wfl + (size_t)(g * 16) * 1024;

        // ---- phase A: s = 0..7 GEMM(g) + gather(g+1) ----
        #pragma unroll
        for (int s = 0; s < 8; ++s) {
            float4 va, vb;
            gatherLDG(g + 1, s, va, vb);
            const uint32_t* wf2 = wfg + (size_t)(s + 2) * 1024;
            uint4 p0 = *(const uint4*)wf2;
            uint4 p1 = *(const uint4*)(wf2 + 128);
            mmaStep(pb, s, u[s & 1][0], u[s & 1][1]);
            u[s & 1][0] = p0; u[s & 1][1] = p1;
            gatherSTS(s, va, vb);
        }
        __syncthreads();   // A(g+1) ready

        // ---- phase B: s = 8..15 GEMM(g) + pconv(g+1) -> P[other] ----
        char* pdst = smc + ((g + 1) & 1) * PBUFB;
        #pragma unroll
        for (int j = 0; j < 8; ++j) {
            pconvPt(j, pdst);
            int s = 8 + j;
            const uint32_t* wf2 = wfg + (size_t)(s + 2) * 1024;
            uint4 p0 = *(const uint4*)wf2;
            uint4 p1 = *(const uint4*)(wf2 + 128);
            mmaStep(pb, s, u[s & 1][0], u[s & 1][1]);
            u[s & 1][0] = p0; u[s & 1][1] = p1;
        }
        __syncthreads();   // P(g+1) ready; A free
    }

    // ---- group 4: 3 real s-steps on P[0] (f < 1072) ----
    {
        const uint32_t pb = 0;   // g=4 -> P[4&1=0]
        const uint32_t* wf2 = wfl + (size_t)66 * 1024;
        uint4 p0 = *(const uint4*)wf2;
        uint4 p1 = *(const uint4*)(wf2 + 128);
        mmaStep(pb, 0, u[0][0], u[0][1]);
        mmaStep(pb, 1, u[1][0], u[1][1]);
        mmaStep(pb, 2, p0, p1);
    }

    // ---- epilogue: bias + store (each warp 32p x 32o) ----
    #pragma unroll
    for (int mt = 0; mt < 2; ++mt) {
        int r = wm * 32 + mt * 16 + (l >> 2);
        #pragma unroll
        for (int nt = 0; nt < 4; ++nt) {
            int o  = wn4 * 32 + nt * 8 + 2 * (l & 3);
            float b0 = bsm[o], b1 = bsm[o + 1];
            int pid = base + r;
            *(float2*)(out + (size_t)pid * 128 + o) =
                make_float2(acc[mt][nt][0] + b0, acc[mt][nt][1] + b1);
            *(float2*)(out + (size_t)(pid + 8) * 128 + o) =
                make_float2(acc[mt][nt][2] + b0, acc[mt][nt][3] + b1);
        }
    }
}

extern "C" void kernel_launch(void* const* d_in, const int* in_sizes, int n_in,
                              void* d_out, int out_size) {
    const float* xin  = (const float*)d_in[0];
    const int*   nbr  = (const int*)d_in[1];
    const float* wng  = (const float*)d_in[2];
    const float* addf = (const float*)d_in[3];
    const float* W    = (const float*)d_in[4];
    const float* bias = (const float*)d_in[5];
    float*       out  = (float*)d_out;

    cudaFuncSetAttribute(pcl_kernel,
                         cudaFuncAttributeMaxDynamicSharedMemorySize, SMEM_BYTES);

    prep_kernel<<<80, 128>>>(W);
    pcl_kernel<<<GRID, THREADS, SMEM_BYTES>>>(xin, nbr, wng, addf, bias, out);
}

// round 16
// speedup vs baseline: 1.1064x; 1.1064x over previous
#include <cuda_runtime.h>
#include <cstdint>

// ---------------------------------------------------------------------------
// PConvLinear, both stages on fp16 mma.sync (m16n8k16), fp32 accumulate.
//   out[p,o] = bias[o] + sum_f P[p,f] * W[o,f],  f = c*16 + m
//   P[p, c*16+m] = sum_{k<16} feat[p,k,c] * wn[p,k,m]
// R16: R14 (Wfrag prefetch distance 2 carried across groups, group-4 trim)
// + gather LDG->STS distance stretched to 4 s-steps (rolling pending pair):
//   blk b: LDG(b+1) ; 2 MMA steps ; STS(b)
// ---------------------------------------------------------------------------

#define NPTS 120000
#define NB   60000
#define TPB  64
#define THREADS 256
#define GRID (NPTS / TPB)      // 1875

// smem byte offsets (R10/R11 proven layout)
#define OFF_P    0             // 64 rows x 528 B   (P tile)
#define OFF_A    33792         // 64 pts x 768 B    (feat tiles, 16r x 48B)
#define OFF_IND  82944         // 1024 ints
#define OFF_BIAS 87040         // 128 floats
#define SMEM_BYTES 87552       // -> 2 CTAs/SM

#define PROWB 528
#define AROWB 48
#define APTB  768

// W fragments: [fs 80][wn4 4][q*128 + l*4]
__device__ uint32_t Wfrag[80 * 1024];

__device__ __forceinline__ uint32_t smem_u32(const void* p) {
    uint32_t a;
    asm("{ .reg .u64 t; cvta.to.shared.u64 t, %1; cvt.u32.u64 %0, t; }"
        : "=r"(a) : "l"(p));
    return a;
}
__device__ __forceinline__ uint32_t pack_f16x2(float lo, float hi) {
    uint32_t r;
    asm("cvt.rn.f16x2.f32 %0, %1, %2;" : "=r"(r) : "f"(hi), "f"(lo));
    return r;
}
__device__ __forceinline__ void ldsm4(uint32_t r[4], uint32_t addr) {
    asm volatile("ldmatrix.sync.aligned.m8n8.x4.shared.b16 {%0,%1,%2,%3}, [%4];"
                 : "=r"(r[0]), "=r"(r[1]), "=r"(r[2]), "=r"(r[3]) : "r"(addr));
}
__device__ __forceinline__ void mma16(float c[4], const uint32_t a[4],
                                      uint32_t b0, uint32_t b1) {
    asm volatile(
        "mma.sync.aligned.m16n8k16.row.col.f32.f16.f16.f32 "
        "{%0,%1,%2,%3}, {%4,%5,%6,%7}, {%8,%9}, {%0,%1,%2,%3};"
        : "+f"(c[0]), "+f"(c[1]), "+f"(c[2]), "+f"(c[3])
        : "r"(a[0]), "r"(a[1]), "r"(a[2]), "r"(a[3]), "r"(b0), "r"(b1));
}

// ---- prep: analytic fp16 B fragments of W (proven) ----
extern "C" __global__ void __launch_bounds__(128, 1)
prep_kernel(const float* __restrict__ W) {
    const int bg = blockIdx.x;           // fs = g*16 + s
    const int t = threadIdx.x, l = t & 31, wn4 = t >> 5;
    const int f0 = (bg >> 4) * 256 + (bg & 15) * 16 + 2 * (l & 3);
    uint32_t r[8];
    #pragma unroll
    for (int nt = 0; nt < 4; ++nt) {
        int o = wn4 * 32 + nt * 8 + (l >> 2);
        const float* wr = W + (size_t)o * 1072;
        float v0 = (f0     < 1072) ? wr[f0]     : 0.f;
        float v1 = (f0 + 1 < 1072) ? wr[f0 + 1] : 0.f;
        float v2 = (f0 + 8 < 1072) ? wr[f0 + 8] : 0.f;
        float v3 = (f0 + 9 < 1072) ? wr[f0 + 9] : 0.f;
        r[nt * 2 + 0] = pack_f16x2(v0, v1);
        r[nt * 2 + 1] = pack_f16x2(v2, v3);
    }
    uint32_t* dst = Wfrag + (bg * 4 + wn4) * 256 + l * 4;
    *(uint4*)dst         = make_uint4(r[0], r[1], r[2], r[3]);
    *(uint4*)(dst + 128) = make_uint4(r[4], r[5], r[6], r[7]);
}

// ---- main ----
extern "C" __global__ void __launch_bounds__(THREADS, 2)
pcl_kernel(const float* __restrict__ xin,   // [2,60000,64]
           const int*   __restrict__ nbr,   // [2,60000,16]
           const float* __restrict__ wng,   // [2,60000,16,16]
           const float* __restrict__ addf,  // [2,60000,16,3]
           const float* __restrict__ bias,  // [128]
           float*       __restrict__ out)   // [2,60000,128]
{
    extern __shared__ __align__(16) char smc[];
    int*   inds = (int*)(smc + OFF_IND);
    float* bsm  = (float*)(smc + OFF_BIAS);

    const uint32_t smb = smem_u32(smc);
    const int t    = threadIdx.x;
    const int wid  = t >> 5;
    const int l    = t & 31;
    const int base = blockIdx.x * TPB;

    // main-GEMM roles
    const int wm  = wid & 1;
    const int wn4 = wid >> 1;

    if (t < 128) bsm[t] = bias[t];

    // ---- neighbor indices: 64 pts x 16 ----
    {
        int pt = base + (t >> 2);
        ((int4*)inds)[t] = *(const int4*)(nbr + (size_t)pt * 16 + (size_t)(t & 3) * 4);
    }

    // ---- pconv B fragments: warp's 8 points, per m-half, from wng ----
    uint32_t bw[8][2][2];
    {
        const int c2 = 2 * (l & 3);
        const int nl = l >> 2;
        #pragma unroll
        for (int j = 0; j < 8; ++j) {
            const float* wp = wng + (size_t)(base + wid * 8 + j) * 256;
            #pragma unroll
            for (int h = 0; h < 2; ++h) {
                int m = h * 8 + nl;
                bw[j][h][0] = pack_f16x2(wp[c2 * 16 + m],       wp[(c2 + 1) * 16 + m]);
                bw[j][h][1] = pack_f16x2(wp[(c2 + 8) * 16 + m], wp[(c2 + 9) * 16 + m]);
            }
        }
    }

    float acc[2][4][4];
    #pragma unroll
    for (int i = 0; i < 2; ++i)
        #pragma unroll
        for (int j = 0; j < 4; ++j)
            #pragma unroll
            for (int q = 0; q < 4; ++q) acc[i][j][q] = 0.f;

    // gather roles (fixed)
    const int gw  = t & 3;
    const int gkp = (t >> 2) & 7;
    const int gp8 = t >> 5;

    auto gatherLDG = [&](int gg, int rep, float4& va, float4& vb) {
        int pp  = rep * 8 + gp8;
        int pid = base + pp;
        if (gg < 4) {
            int k0   = 2 * gkp;
            int nb0  = inds[pp * 16 + k0];
            int nb1  = inds[pp * 16 + k0 + 1];
            int brow = (pid >= NB) ? NB : 0;
            va = *(const float4*)(xin + (size_t)(brow + nb0) * 64 + gg * 16 + gw * 4);
            vb = *(const float4*)(xin + (size_t)(brow + nb1) * 64 + gg * 16 + gw * 4);
        } else {
            va = make_float4(0.f, 0.f, 0.f, 0.f);
            vb = make_float4(0.f, 0.f, 0.f, 0.f);
            if (gw == 0) {
                const float* a0 = addf + ((size_t)pid * 16 + 2 * gkp) * 3;
                va.x = a0[0]; va.y = a0[1]; va.z = a0[2];
                vb.x = a0[3]; vb.y = a0[4]; vb.z = a0[5];
            }
        }
    };
    auto gatherSTS = [&](int rep, const float4& va, const float4& vb) {
        int pp = rep * 8 + gp8;
        uint32_t* dst = (uint32_t*)(smc + OFF_A + pp * APTB + gw * 4 * AROWB) + gkp;
        dst[0 * 12] = pack_f16x2(va.x, vb.x);
        dst[1 * 12] = pack_f16x2(va.y, vb.y);
        dst[2 * 12] = pack_f16x2(va.z, vb.z);
        dst[3 * 12] = pack_f16x2(va.w, vb.w);
    };

    __syncthreads();   // inds visible

    // ---- prologue gather: group 0 ----
    #pragma unroll
    for (int rep = 0; rep < 8; ++rep) {
        float4 va, vb;
        gatherLDG(0, rep, va, vb);
        gatherSTS(rep, va, vb);
    }

    // ---- Wfrag rolling prefetch slots: init with fs 0 and 1 ----
    const uint32_t* wfl = Wfrag + wn4 * 256 + l * 4;
    uint4 u[2][2];
    u[0][0] = *(const uint4*)wfl;
    u[0][1] = *(const uint4*)(wfl + 128);
    u[1][0] = *(const uint4*)(wfl + 1024);
    u[1][1] = *(const uint4*)(wfl + 1024 + 128);

    __syncthreads();   // A ready

    // role constants
    const int rr = l >> 2;
    const int mc = 2 * (l & 3);
    const uint32_t arow = smb + (uint32_t)((wm * 32 + (l & 15)) * PROWB
                                           + (l >> 4) * 16);
    const uint32_t aoff = (uint32_t)((l & 15) * AROWB + (l >> 4) * 16);

    auto mmaStep = [&](int s, const uint4& U0, const uint4& U1) {
        #pragma unroll
        for (int mt = 0; mt < 2; ++mt) {
            uint32_t a[4];
            ldsm4(a, arow + (uint32_t)(mt * 16 * PROWB + s * 32));
            mma16(acc[mt][0], a, U0.x, U0.y);
            mma16(acc[mt][1], a, U0.z, U0.w);
            mma16(acc[mt][2], a, U1.x, U1.y);
            mma16(acc[mt][3], a, U1.z, U1.w);
        }
    };

    for (int g = 0; g < 5; ++g) {
        // ---- pconv(g): per warp 8 points; 1 ldsm + 2 MMA + 4 STS ----
        #pragma unroll
        for (int j = 0; j < 8; ++j) {
            int ptl = wid * 8 + j;
            uint32_t a[4];
            ldsm4(a, smb + OFF_A + (uint32_t)(ptl * APTB) + aoff);
            char* prow = smc + OFF_P + ptl * PROWB;
            #pragma unroll
            for (int h = 0; h < 2; ++h) {
                float c[4] = {0.f, 0.f, 0.f, 0.f};
                mma16(c, a, bw[j][h][0], bw[j][h][1]);
                int fl = rr * 16 + h * 8 + mc;
                *(uint32_t*)(prow + fl * 2)         = pack_f16x2(c[0], c[1]);
                *(uint32_t*)(prow + (fl + 128) * 2) = pack_f16x2(c[2], c[3]);
            }
        }
        __syncthreads();   // P ready; A free

        const uint32_t* wfg = wfl + (size_t)(g * 16) * 1024;

        if (g < 4) {
            // ---- mainGEMM(g), 16 s-steps; gather(g+1) LDG->STS dist 4 ----
            float4 vaP, vbP;                 // pending pair (STS one blk later)
            gatherLDG(g + 1, 0, vaP, vbP);
            #pragma unroll
            for (int blk = 0; blk < 8; ++blk) {
                float4 vaN, vbN;
                if (blk < 7) gatherLDG(g + 1, blk + 1, vaN, vbN);
                #pragma unroll
                for (int ss = 0; ss < 2; ++ss) {
                    int s = blk * 2 + ss;
                    // prefetch fs = g*16 + s + 2 (contiguous; crosses groups)
                    const uint32_t* wf2 = wfg + (size_t)(s + 2) * 1024;
                    uint4 p0 = *(const uint4*)wf2;
                    uint4 p1 = *(const uint4*)(wf2 + 128);
                    mmaStep(s, u[ss][0], u[ss][1]);
                    u[ss][0] = p0; u[ss][1] = p1;
                }
                gatherSTS(blk, vaP, vbP);
                vaP = vaN; vbP = vbN;
            }
        } else {
            // ---- group 4: only 3 real s-steps (f < 1072) ----
            const uint32_t* wf2 = wfg + (size_t)2 * 1024;
            uint4 p0 = *(const uint4*)wf2;           // fs 66 (last real)
            uint4 p1 = *(const uint4*)(wf2 + 128);
            mmaStep(0, u[0][0], u[0][1]);
            mmaStep(1, u[1][0], u[1][1]);
            mmaStep(2, p0, p1);
        }
        __syncthreads();   // A(g+1) ready; P free
    }

    // ---- epilogue: bias + store (each warp 32p x 32o) ----
    #pragma unroll
    for (int mt = 0; mt < 2; ++mt) {
        int r = wm * 32 + mt * 16 + (l >> 2);
        #pragma unroll
        for (int nt = 0; nt < 4; ++nt) {
            int o  = wn4 * 32 + nt * 8 + 2 * (l & 3);
            float b0 = bsm[o], b1 = bsm[o + 1];
            int pid = base + r;
            *(float2*)(out + (size_t)pid * 128 + o) =
                make_float2(acc[mt][nt][0] + b0, acc[mt][nt][1] + b1);
            *(float2*)(out + (size_t)(pid + 8) * 128 + o) =
                make_float2(acc[mt][nt][2] + b0, acc[mt][nt][3] + b1);
        }
    }
}

extern "C" void kernel_launch(void* const* d_in, const int* in_sizes, int n_in,
                              void* d_out, int out_size) {
    const float* xin  = (const float*)d_in[0];
    const int*   nbr  = (const int*)d_in[1];
    const float* wng  = (const float*)d_in[2];
    const float* addf = (const float*)d_in[3];
    const float* W    = (const float*)d_in[4];
    const float* bias = (const float*)d_in[5];
    float*       out  = (float*)d_out;

    cudaFuncSetAttribute(pcl_kernel,
                         cudaFuncAttributeMaxDynamicSharedMemorySize, SMEM_BYTES);

    prep_kernel<<<80, 128>>>(W);
    pcl_kernel<<<GRID, THREADS, SMEM_BYTES>>>(xin, nbr, wng, addf, bias, out);
}